// round 5
// baseline (speedup 1.0000x reference)
#include <cuda_runtime.h>

#define T_LEN 4096
#define D_DIM 1024
#define NCTA  128
#define CPC   8      // columns per CTA (= warps per CTA)

typedef unsigned long long ull;

// ---------------- scratch (device globals: no allocation allowed) -----------
__device__ float    g_Gr[T_LEN * D_DIM];
__device__ float    g_Gz[T_LEN * D_DIM];
__device__ float    g_Gn[T_LEN * D_DIM];
__device__ float    g_ys[T_LEN * D_DIM];        // h history (recurrence + post GEMM)
__device__ unsigned g_flag[NCTA * 32];          // per-CTA step flag, 128B stride

// ---------------- PTX helpers ----------------------------------------------
__device__ __forceinline__ ull pack2(float lo, float hi) {
    ull r;
    asm("mov.b64 %0, {%1, %2};" : "=l"(r) : "f"(lo), "f"(hi));
    return r;
}
__device__ __forceinline__ void unpack2(ull v, float& lo, float& hi) {
    asm("mov.b64 {%0, %1}, %2;" : "=f"(lo), "=f"(hi) : "l"(v));
}
__device__ __forceinline__ void fma2(ull& d, ull a, ull b) {
    asm("fma.rn.f32x2 %0, %1, %2, %0;" : "+l"(d) : "l"(a), "l"(b));
}
__device__ __forceinline__ unsigned ld_acquire(const unsigned* p) {
    unsigned v;
    asm volatile("ld.acquire.gpu.u32 %0, [%1];" : "=r"(v) : "l"(p));
    return v;
}
__device__ __forceinline__ void st_release(unsigned* p, unsigned v) {
    asm volatile("st.release.gpu.u32 [%0], %1;" :: "l"(p), "r"(v));
}

// ---------------- flag clear (fresh each graph replay) ----------------------
__global__ void clear_flags_kernel() {
    g_flag[threadIdx.x * 32] = 0u;     // 128 threads, 1 block
}

// ---------------- fp32x2 GEMM: C = (relu?)(A) @ B + bias, 128x128 / 8x8 ----
template <bool RELU_A>
__global__ void __launch_bounds__(256) gemm128_kernel(
    const float* __restrict__ A, const float* __restrict__ B,
    const float* __restrict__ bias, float* __restrict__ C,
    int M, int N, int K)
{
    __shared__ float As[8][128];   // As[k][m] (transposed)
    __shared__ float Bs[8][128];   // Bs[k][n]

    const int tid = threadIdx.x;
    const int bm = blockIdx.y << 7, bn = blockIdx.x << 7;

    const int arow = tid >> 1;             // 0..127
    const int acol = (tid & 1) << 2;       // 0 or 4
    const int brow = tid >> 5;             // 0..7
    const int bcol = (tid & 31) << 2;      // 0..124

    const float* Ap = A + (size_t)(bm + arow) * K + acol;
    const float* Bp = B + (size_t)brow * N + bn + bcol;

    const int tx = tid & 15, ty = tid >> 4;

    ull accp[8][4];                        // 8 m-rows x 4 packed n-pairs
#pragma unroll
    for (int i = 0; i < 8; i++)
#pragma unroll
        for (int j = 0; j < 4; j++) accp[i][j] = 0ull;

    float4 a4 = *(const float4*)Ap;
    float4 b4 = *(const float4*)Bp;

    for (int kb = 0; kb < K; kb += 8) {
        float4 av = a4, bv = b4;
        if (RELU_A) {
            av.x = fmaxf(av.x, 0.f); av.y = fmaxf(av.y, 0.f);
            av.z = fmaxf(av.z, 0.f); av.w = fmaxf(av.w, 0.f);
        }
        As[acol + 0][arow] = av.x;
        As[acol + 1][arow] = av.y;
        As[acol + 2][arow] = av.z;
        As[acol + 3][arow] = av.w;
        *(float4*)&Bs[brow][bcol] = bv;
        __syncthreads();

        if (kb + 8 < K) {                       // prefetch next k-slice
            a4 = *(const float4*)(Ap + kb + 8);
            b4 = *(const float4*)(Bp + (size_t)(kb + 8) * N);
        }

#pragma unroll
        for (int kk = 0; kk < 8; kk++) {
            float a8[8];
            *(float4*)(a8)     = *(const float4*)&As[kk][ty << 3];
            *(float4*)(a8 + 4) = *(const float4*)&As[kk][(ty << 3) + 4];
            const ull* bsp = (const ull*)&Bs[kk][tx << 3];   // 4 packed pairs
            ull b0 = bsp[0], b1 = bsp[1], b2 = bsp[2], b3 = bsp[3];
#pragma unroll
            for (int i = 0; i < 8; i++) {
                ull ai = pack2(a8[i], a8[i]);
                fma2(accp[i][0], ai, b0);
                fma2(accp[i][1], ai, b1);
                fma2(accp[i][2], ai, b2);
                fma2(accp[i][3], ai, b3);
            }
        }
        __syncthreads();
    }

    float bb[8];
    *(float4*)(bb)     = *(const float4*)&bias[bn + (tx << 3)];
    *(float4*)(bb + 4) = *(const float4*)&bias[bn + (tx << 3) + 4];
#pragma unroll
    for (int i = 0; i < 8; i++) {
        float c[8];
        unpack2(accp[i][0], c[0], c[1]);
        unpack2(accp[i][1], c[2], c[3]);
        unpack2(accp[i][2], c[4], c[5]);
        unpack2(accp[i][3], c[6], c[7]);
        float* Cp = C + (size_t)(bm + (ty << 3) + i) * N + bn + (tx << 3);
        *(float4*)(Cp)     = make_float4(c[0] + bb[0], c[1] + bb[1],
                                         c[2] + bb[2], c[3] + bb[3]);
        *(float4*)(Cp + 4) = make_float4(c[4] + bb[4], c[5] + bb[5],
                                         c[6] + bb[6], c[7] + bb[7]);
    }
}

// ---------------- persistent GRU recurrence ---------------------------------
// 128 CTAs x 256 threads. Warp w owns global column cta*8 + w.
// Weights in registers. Sync: per-CTA monotonic flag (release/acquire);
// each consumer thread polls exactly the flag covering the float4 it reads.
__global__ void __launch_bounds__(256, 1) gru_recurrence_kernel(
    const float* __restrict__ Whr, const float* __restrict__ Whz,
    const float* __restrict__ Whn, const float* __restrict__ bhn,
    const float* __restrict__ init_state)
{
    __shared__ float sh_h[D_DIM];          // h_{t-1} (single buffer)

    const int tid  = threadIdx.x;
    const int warp = tid >> 5, lane = tid & 31;
    const int col  = blockIdx.x * CPC + warp;

    // ---- one-time: weight slice into registers (48 packed f32x2 / gate) ----
    ull wr[16], wz[16], wn[16];
#pragma unroll
    for (int i = 0; i < 16; i++) {
        const int k0 = 2 * (lane + 32 * i);
        const size_t o0 = (size_t)k0 * D_DIM + col;
        const size_t o1 = (size_t)(k0 + 1) * D_DIM + col;
        wr[i] = pack2(Whr[o0], Whr[o1]);
        wz[i] = pack2(Whz[o0], Whz[o1]);
        wn[i] = pack2(Whn[o0], Whn[o1]);
    }
    const float bhn_c = bhn[col];

    float h_prev = init_state[col];
    float gr_c = g_Gr[col], gz_c = g_Gz[col], gn_c = g_Gn[col];

    const unsigned* my_poll = &g_flag[(tid >> 1) * 32];   // producer of my float4
    unsigned* my_flag = &g_flag[blockIdx.x * 32];

    for (int t = 0; t < T_LEN; t++) {
        // ---- prefetch next step's gate pre-activations (off critical path) --
        float grn = 0.f, gzn = 0.f, gnn = 0.f;
        if (lane == 0 && t + 1 < T_LEN) {
            const size_t o = (size_t)(t + 1) * D_DIM + col;
            grn = __ldg(&g_Gr[o]); gzn = __ldg(&g_Gz[o]); gnn = __ldg(&g_Gn[o]);
        }

        // ---- stage h_{t-1}: per-thread acquire on owning producer's flag ----
        if (t == 0) {
            float4 v = ((const float4*)init_state)[tid];
            *(float4*)&sh_h[tid << 2] = v;
        } else {
            while (ld_acquire(my_poll) < (unsigned)t) {}
            float4 hv = *(const float4*)(g_ys + (size_t)(t - 1) * D_DIM + (tid << 2));
            *(float4*)&sh_h[tid << 2] = hv;
        }
        __syncthreads();

        // ---- packed dot products (3 gates, 2 accumulators each) ----
        const ull* h2 = (const ull*)sh_h;
        ull ar0 = 0, ar1 = 0, az0 = 0, az1 = 0, an0 = 0, an1 = 0;
#pragma unroll
        for (int i = 0; i < 16; i += 2) {
            ull h0 = h2[lane + 32 * i];
            ull h1 = h2[lane + 32 * (i + 1)];
            fma2(ar0, h0, wr[i]);  fma2(ar1, h1, wr[i + 1]);
            fma2(az0, h0, wz[i]);  fma2(az1, h1, wz[i + 1]);
            fma2(an0, h0, wn[i]);  fma2(an1, h1, wn[i + 1]);
        }
        float lo, hi, ar, az, an;
        unpack2(ar0, lo, hi); ar = lo + hi; unpack2(ar1, lo, hi); ar += lo + hi;
        unpack2(az0, lo, hi); az = lo + hi; unpack2(az1, lo, hi); az += lo + hi;
        unpack2(an0, lo, hi); an = lo + hi; unpack2(an1, lo, hi); an += lo + hi;

#pragma unroll
        for (int o = 16; o > 0; o >>= 1) {
            ar += __shfl_xor_sync(0xFFFFFFFFu, ar, o);
            az += __shfl_xor_sync(0xFFFFFFFFu, az, o);
            an += __shfl_xor_sync(0xFFFFFFFFu, an, o);
        }

        // ---- gate math + publish (lane 0 of each warp) ----
        if (lane == 0) {
            float er = __expf(-(gr_c + ar));
            float r  = __fdividef(1.f, 1.f + er);
            float ez = __expf(-(gz_c + az));
            float z  = __fdividef(1.f, 1.f + ez);
            float nx = gn_c + r * (an + bhn_c);
            float en = __expf(-2.f * nx);
            float n  = __fdividef(1.f - en, 1.f + en);      // tanh(nx)
            float hnew = n + z * (h_prev - n);
            g_ys[(size_t)t * D_DIM + col] = hnew;
            h_prev = hnew;
            gr_c = grn; gz_c = gzn; gn_c = gnn;
        }
        __syncthreads();                   // 8 column stores done; smem reusable

        if (tid == 0) st_release(my_flag, (unsigned)(t + 1));
    }
}

// ---------------- residual + layernorm (in-place on d_out) -----------------
__global__ void __launch_bounds__(256) layernorm_kernel(
    const float* __restrict__ xs, const float* __restrict__ ln_scale,
    const float* __restrict__ ln_bias, float* __restrict__ inout)
{
    __shared__ float red0[8], red1[8];
    const int t = blockIdx.x, tid = threadIdx.x;
    const float* xrow = xs + (size_t)t * D_DIM;
    float* yrow = inout + (size_t)t * D_DIM;

    float v[4];
    float s = 0.f, s2 = 0.f;
#pragma unroll
    for (int i = 0; i < 4; i++) {
        int idx = tid + i * 256;
        float y = xrow[idx] + yrow[idx];
        v[i] = y; s += y; s2 += y * y;
    }
#pragma unroll
    for (int o = 16; o > 0; o >>= 1) {
        s  += __shfl_xor_sync(0xFFFFFFFFu, s,  o);
        s2 += __shfl_xor_sync(0xFFFFFFFFu, s2, o);
    }
    const int warp = tid >> 5, lane = tid & 31;
    if (lane == 0) { red0[warp] = s; red1[warp] = s2; }
    __syncthreads();
    if (warp == 0) {
        float a = (lane < 8) ? red0[lane] : 0.f;
        float b = (lane < 8) ? red1[lane] : 0.f;
#pragma unroll
        for (int o = 4; o > 0; o >>= 1) {
            a += __shfl_xor_sync(0xFFFFFFFFu, a, o);
            b += __shfl_xor_sync(0xFFFFFFFFu, b, o);
        }
        if (lane == 0) { red0[0] = a; red1[0] = b; }
    }
    __syncthreads();

    const float mu   = red0[0] * (1.f / D_DIM);
    const float var  = red1[0] * (1.f / D_DIM) - mu * mu;
    const float rstd = rsqrtf(var + 1e-6f);
#pragma unroll
    for (int i = 0; i < 4; i++) {
        int idx = tid + i * 256;
        yrow[idx] = (v[i] - mu) * rstd * ln_scale[idx] + ln_bias[idx];
    }
}

// ---------------- launcher --------------------------------------------------
extern "C" void kernel_launch(void* const* d_in, const int* in_sizes, int n_in,
                              void* d_out, int out_size)
{
    const float* xs        = (const float*)d_in[0];
    const float* init_st   = (const float*)d_in[1];
    const float* Wir       = (const float*)d_in[2];
    const float* Wiz       = (const float*)d_in[3];
    const float* Win       = (const float*)d_in[4];
    const float* bir       = (const float*)d_in[5];
    const float* biz       = (const float*)d_in[6];
    const float* bin_      = (const float*)d_in[7];
    const float* Whr       = (const float*)d_in[8];
    const float* Whz       = (const float*)d_in[9];
    const float* Whn       = (const float*)d_in[10];
    const float* bhn       = (const float*)d_in[11];
    const float* Wl        = (const float*)d_in[12];
    const float* bl        = (const float*)d_in[13];
    const float* ln_scale  = (const float*)d_in[14];
    const float* ln_bias   = (const float*)d_in[15];
    float* out = (float*)d_out;

    void *pGr, *pGz, *pGn, *pYs;
    cudaGetSymbolAddress(&pGr, g_Gr);
    cudaGetSymbolAddress(&pGz, g_Gz);
    cudaGetSymbolAddress(&pGn, g_Gn);
    cudaGetSymbolAddress(&pYs, g_ys);

    dim3 gemm_grid(D_DIM / 128, T_LEN / 128);   // (8, 32)

    // 1) clear per-CTA step flags (graph-replay determinism)
    clear_flags_kernel<<<1, NCTA>>>();

    // 2) input-side gate pre-GEMMs (parallel over time)
    gemm128_kernel<false><<<gemm_grid, 256>>>(xs, Wir, bir, (float*)pGr,
                                              T_LEN, D_DIM, D_DIM);
    gemm128_kernel<false><<<gemm_grid, 256>>>(xs, Wiz, biz, (float*)pGz,
                                              T_LEN, D_DIM, D_DIM);
    gemm128_kernel<false><<<gemm_grid, 256>>>(xs, Win, bin_, (float*)pGn,
                                              T_LEN, D_DIM, D_DIM);

    // 3) sequential recurrence: persistent grid, register-resident weights
    gru_recurrence_kernel<<<NCTA, 256>>>(Whr, Whz, Whn, bhn, init_st);

    // 4) post dense: d_out = relu(ys) @ Wl + bl
    gemm128_kernel<true><<<gemm_grid, 256>>>((const float*)pYs, Wl, bl, out,
                                             T_LEN, D_DIM, D_DIM);

    // 5) residual + layernorm in-place on d_out
    layernorm_kernel<<<T_LEN, 256>>>(xs, ln_scale, ln_bias, out);
}